// round 14
// baseline (speedup 1.0000x reference)
#include <cuda_runtime.h>
#include <cuda_fp16.h>
#include <cuda_bf16.h>

// out[row[e]] += values[e] * x[col[e]],  row sorted ascending.
// E = 1.6M, N = 100k, D = 64.
//
// Edge-balanced formulation:
//   - warp = 4 groups x 8 lanes; group owns CHUNK=32 consecutive edges.
//   - lane fl gathers one uint4 (16B fp16) per edge -> 8 lanes cover the full
//     128B fp16 feature row: exactly one L2 line per edge.
//   - flush points precomputed in prep as a 32-bit mask per chunk; main loop
//     does NOT read row[] except inside (rare) flush steps.
//   - segment flush via predicated red.global.add.v4.f32, gated by a
//     warp-uniform ballot so RED/SEL issue only on boundary steps.
// Prep (1 fused kernel, 3 block ranges): x->fp16 convert, out zero-init,
// flush-flag build.

#define N_NODES 100000
#define D_FEAT 64
#define CHUNK 32
#define MAX_CHUNKS 50016

__device__ __align__(256) __half g_x_half[(size_t)N_NODES * D_FEAT];
__device__ unsigned g_flags[MAX_CHUNKS];

__global__ void __launch_bounds__(256) fused_prep_kernel(
    const float* __restrict__ x, int n8,        // convert: n8 = floats/8
    float* __restrict__ out, int n_out8,        // zero: out floats/8
    const int* __restrict__ row, int n_edges,   // flags
    int n_chunks, int conv_blocks, int zero_blocks)
{
    int b = blockIdx.x;
    if (b < conv_blocks) {
        int i = b * blockDim.x + threadIdx.x;
        if (i >= n8) return;
        const float4* x4 = (const float4*)x;
        float4 f0 = __ldg(&x4[2 * i]);
        float4 f1 = __ldg(&x4[2 * i + 1]);
        __half2 h0 = __floats2half2_rn(f0.x, f0.y);
        __half2 h1 = __floats2half2_rn(f0.z, f0.w);
        __half2 h2 = __floats2half2_rn(f1.x, f1.y);
        __half2 h3 = __floats2half2_rn(f1.z, f1.w);
        uint4 p;
        p.x = *(unsigned*)&h0; p.y = *(unsigned*)&h1;
        p.z = *(unsigned*)&h2; p.w = *(unsigned*)&h3;
        ((uint4*)g_x_half)[i] = p;
    } else if (b < conv_blocks + zero_blocks) {
        int i = (b - conv_blocks) * blockDim.x + threadIdx.x;
        if (i >= n_out8) return;
        float4 z = make_float4(0.f, 0.f, 0.f, 0.f);
        ((float4*)out)[2 * i]     = z;
        ((float4*)out)[2 * i + 1] = z;
    } else {
        int c = (b - conv_blocks - zero_blocks) * blockDim.x + threadIdx.x;
        if (c >= n_chunks) return;
        int base = c * CHUNK;
        int last = n_edges - 1;
        unsigned flags = 0;
        int r_prev = __ldg(&row[min(base, last)]);
        #pragma unroll 8
        for (int j = 0; j < CHUNK; ++j) {
            int e = base + j;
            int r_next = __ldg(&row[min(e + 1, last)]);
            int flush = (j == CHUNK - 1) || (e == last) ||
                        ((e < last) && (r_next != r_prev));
            flags |= (unsigned)flush << j;
            r_prev = r_next;
        }
        g_flags[c] = flags;
    }
}

__device__ __forceinline__ void red_add_v4(float* addr, float a, float b,
                                           float c, float d, int pred) {
    asm volatile(
        "{\n\t"
        ".reg .pred p;\n\t"
        "setp.ne.s32 p, %0, 0;\n\t"
        "@p red.global.add.v4.f32 [%1], {%2, %3, %4, %5};\n\t"
        "}" :: "r"(pred), "l"(addr), "f"(a), "f"(b), "f"(c), "f"(d) : "memory");
}

__global__ void __launch_bounds__(256) spmm_edge_chunk_kernel(
    const int* __restrict__ row,
    const int* __restrict__ col,
    const float* __restrict__ val,
    float* __restrict__ out,
    int n_edges)
{
    int gwarp = (blockIdx.x * blockDim.x + threadIdx.x) >> 5;
    int lane  = threadIdx.x & 31;
    int grp   = lane >> 3;          // which 32-edge chunk of this warp
    int fl    = lane & 7;           // owns fp16 feats [8*fl, 8*fl+8)

    int chunk = gwarp * 4 + grp;
    int base  = chunk * CHUNK;
    int warp_base = gwarp * 4 * CHUNK;

    const uint4* __restrict__ xq = (const uint4*)g_x_half;  // 8 uint4 per row

    float acc[8];
    #pragma unroll
    for (int k = 0; k < 8; ++k) acc[k] = 0.f;

    if (warp_base + 4 * CHUNK <= n_edges) {
        // ---------- clean path: whole warp strictly inside [0, n_edges) ----------
        unsigned flags = __ldg(&g_flags[chunk]);

        #pragma unroll 8
        for (int j = 0; j < CHUNK; ++j) {
            int idx = base + j;
            int   c = __ldg(&col[idx]);
            float v = __ldg(&val[idx]);

            uint4 raw = __ldg(&xq[(size_t)c * (D_FEAT / 8) + fl]);  // 128B line
            const __half2* hp = reinterpret_cast<const __half2*>(&raw);
            #pragma unroll
            for (int k = 0; k < 4; ++k) {
                float2 f = __half22float2(hp[k]);
                acc[2 * k]     = fmaf(v, f.x, acc[2 * k]);
                acc[2 * k + 1] = fmaf(v, f.y, acc[2 * k + 1]);
            }

            int flush = (flags >> j) & 1;
            if (__ballot_sync(0xffffffffu, flush)) {      // rare: ~8/32 steps
                int r = __ldg(&row[idx]);                 // only on flush steps
                float* dst = out + (size_t)r * D_FEAT + fl * 8;
                red_add_v4(dst,     acc[0], acc[1], acc[2], acc[3], flush);
                red_add_v4(dst + 4, acc[4], acc[5], acc[6], acc[7], flush);
                #pragma unroll
                for (int k = 0; k < 8; ++k) acc[k] = flush ? 0.f : acc[k];
            }
        }
    } else {
        // ---------- guarded tail path (last warp only) ----------
        int last = n_edges - 1;
        if (last < 0) return;
        unsigned flags = (base <= last) ? __ldg(&g_flags[chunk]) : 0u;

        #pragma unroll 8
        for (int j = 0; j < CHUNK; ++j) {
            int idx  = base + j;
            int idxc = min(idx, last);
            int   c = __ldg(&col[idxc]);
            float v = (idx <= last) ? __ldg(&val[idxc]) : 0.f;

            uint4 raw = __ldg(&xq[(size_t)c * (D_FEAT / 8) + fl]);
            const __half2* hp = reinterpret_cast<const __half2*>(&raw);
            #pragma unroll
            for (int k = 0; k < 4; ++k) {
                float2 f = __half22float2(hp[k]);
                acc[2 * k]     = fmaf(v, f.x, acc[2 * k]);
                acc[2 * k + 1] = fmaf(v, f.y, acc[2 * k + 1]);
            }

            int flush = (flags >> j) & 1;
            if (__ballot_sync(0xffffffffu, flush)) {
                int r = __ldg(&row[idxc]);
                float* dst = out + (size_t)r * D_FEAT + fl * 8;
                red_add_v4(dst,     acc[0], acc[1], acc[2], acc[3], flush);
                red_add_v4(dst + 4, acc[4], acc[5], acc[6], acc[7], flush);
                #pragma unroll
                for (int k = 0; k < 8; ++k) acc[k] = flush ? 0.f : acc[k];
            }
        }
    }
}

extern "C" void kernel_launch(void* const* d_in, const int* in_sizes, int n_in,
                              void* d_out, int out_size) {
    const int*   row = (const int*)d_in[0];
    const int*   col = (const int*)d_in[1];
    const float* val = (const float*)d_in[2];
    const float* x   = (const float*)d_in[3];
    float*       out = (float*)d_out;

    int n_edges = in_sizes[0];
    int n_x     = in_sizes[3];
    int n_chunks = (n_edges + CHUNK - 1) / CHUNK;

    {
        int threads = 256;
        int n8     = n_x / 8;
        int n_out8 = out_size / 8;
        int conv_blocks = (n8 + threads - 1) / threads;
        int zero_blocks = (n_out8 + threads - 1) / threads;
        int flag_blocks = (n_chunks + threads - 1) / threads;
        fused_prep_kernel<<<conv_blocks + zero_blocks + flag_blocks, threads>>>(
            x, n8, out, n_out8, row, n_edges, n_chunks, conv_blocks, zero_blocks);
    }
    {
        int threads = 256;  // 8 warps/block; warp covers 4*CHUNK = 128 edges
        long warps = ((long)n_chunks + 3) / 4;
        int blocks = (int)((warps * 32 + threads - 1) / threads);
        spmm_edge_chunk_kernel<<<blocks, threads>>>(row, col, val, out, n_edges);
    }
}

// round 15
// speedup vs baseline: 1.5208x; 1.5208x over previous
#include <cuda_runtime.h>
#include <cuda_fp16.h>
#include <cuda_bf16.h>

// out[row[e]] += values[e] * x[col[e]],  row sorted ascending.
// E = 1.6M, N = 100k, D = 64.
//
// Edge-balanced formulation (R13 body + persistent grid-stride scheduling):
//   - warp-task = 4 groups x 8 lanes; group owns CHUNK=16 consecutive edges.
//   - lane fl gathers one uint4 (16B fp16) per edge -> 8 lanes cover the full
//     128B fp16 feature row: exactly one L2 line per edge.
//   - row-boundary flush via predicated red.global.add.v4.f32, gated by a
//     warp-uniform ballot so RED/SEL only issue on boundary steps.
//   - PERSISTENT grid (1216 blocks = resident capacity): warps grid-stride
//     over tasks -> no wave quantization (R13 had 2.64 waves, ~13% tail loss;
//     R14's 1.32 waves caused the regression).
// Prep (1 fused kernel): x->fp16 convert + out zero-init (R13 proven).

#define N_NODES 100000
#define D_FEAT 64
#define CHUNK 16

__device__ __align__(256) __half g_x_half[(size_t)N_NODES * D_FEAT];

__global__ void __launch_bounds__(256) fused_prep_kernel(
    const float* __restrict__ x, int n4,   // convert job: n4 = floats/4
    float* __restrict__ out, int n_out4,   // zero job: out_size/4
    int conv_blocks)
{
    if ((int)blockIdx.x < conv_blocks) {
        int i = blockIdx.x * blockDim.x + threadIdx.x;
        if (i >= n4) return;
        float4 f = __ldg(&((const float4*)x)[i]);
        __half2 h0 = __floats2half2_rn(f.x, f.y);
        __half2 h1 = __floats2half2_rn(f.z, f.w);
        uint2 packed;
        packed.x = *(unsigned*)&h0;
        packed.y = *(unsigned*)&h1;
        ((uint2*)g_x_half)[i] = packed;
    } else {
        int i = (blockIdx.x - conv_blocks) * blockDim.x + threadIdx.x;
        if (i >= n_out4) return;
        ((float4*)out)[i] = make_float4(0.f, 0.f, 0.f, 0.f);
    }
}

__device__ __forceinline__ void red_add_v4(float* addr, float a, float b,
                                           float c, float d, int pred) {
    asm volatile(
        "{\n\t"
        ".reg .pred p;\n\t"
        "setp.ne.s32 p, %0, 0;\n\t"
        "@p red.global.add.v4.f32 [%1], {%2, %3, %4, %5};\n\t"
        "}" :: "r"(pred), "l"(addr), "f"(a), "f"(b), "f"(c), "f"(d) : "memory");
}

__global__ void __launch_bounds__(256) spmm_edge_chunk_kernel(
    const int* __restrict__ row,
    const int* __restrict__ col,
    const float* __restrict__ val,
    float* __restrict__ out,
    int n_edges, int n_tasks)
{
    int lane = threadIdx.x & 31;
    int wid  = threadIdx.x >> 5;
    int grp  = lane >> 3;           // which 16-edge chunk of this warp-task
    int fl   = lane & 7;            // owns fp16 feats [8*fl, 8*fl+8)

    const uint4* __restrict__ xq = (const uint4*)g_x_half;  // 8 uint4 per row
    int warps_per_grid = gridDim.x * (blockDim.x >> 5);

    for (int task = blockIdx.x * (blockDim.x >> 5) + wid;
         task < n_tasks;
         task += warps_per_grid) {

        int warp_base = task * (4 * CHUNK);
        int base = warp_base + grp * CHUNK;

        float acc[8];
        #pragma unroll
        for (int k = 0; k < 8; ++k) acc[k] = 0.f;

        if (warp_base + 4 * CHUNK <= n_edges) {
            // ---------- clean path: whole warp-task inside [0, n_edges) ----------
            int r_cur = __ldg(&row[base]);

            #pragma unroll
            for (int j = 0; j < CHUNK; ++j) {
                int idx = base + j;
                int   c = __ldg(&col[idx]);
                float v = __ldg(&val[idx]);

                uint4 raw = __ldg(&xq[(size_t)c * (D_FEAT / 8) + fl]); // 128B line
                const __half2* hp = reinterpret_cast<const __half2*>(&raw);
                #pragma unroll
                for (int k = 0; k < 4; ++k) {
                    float2 f = __half22float2(hp[k]);
                    acc[2 * k]     = fmaf(v, f.x, acc[2 * k]);
                    acc[2 * k + 1] = fmaf(v, f.y, acc[2 * k + 1]);
                }

                int flush, r_next;
                if (j == CHUNK - 1) {
                    flush = 1; r_next = r_cur;            // chunk end: always flush
                } else {
                    r_next = __ldg(&row[idx + 1]);        // L1 broadcast hit
                    flush = (r_next != r_cur);
                }

                if (__ballot_sync(0xffffffffu, flush)) {  // warp-uniform gate
                    float* dst = out + (size_t)r_cur * D_FEAT + fl * 8;
                    red_add_v4(dst,     acc[0], acc[1], acc[2], acc[3], flush);
                    red_add_v4(dst + 4, acc[4], acc[5], acc[6], acc[7], flush);
                    #pragma unroll
                    for (int k = 0; k < 8; ++k) acc[k] = flush ? 0.f : acc[k];
                }
                r_cur = r_next;
            }
        } else {
            // ---------- guarded tail path (last warp-task only) ----------
            int last = n_edges - 1;
            if (last < 0) continue;
            int r_cur = __ldg(&row[min(base, last)]);

            #pragma unroll
            for (int j = 0; j < CHUNK; ++j) {
                int idx  = base + j;
                int idxc = min(idx, last);
                int   c = __ldg(&col[idxc]);
                float v = (idx <= last) ? __ldg(&val[idxc]) : 0.f;
                int r_next = __ldg(&row[min(idx + 1, last)]);

                uint4 raw = __ldg(&xq[(size_t)c * (D_FEAT / 8) + fl]);
                const __half2* hp = reinterpret_cast<const __half2*>(&raw);
                #pragma unroll
                for (int k = 0; k < 4; ++k) {
                    float2 f = __half22float2(hp[k]);
                    acc[2 * k]     = fmaf(v, f.x, acc[2 * k]);
                    acc[2 * k + 1] = fmaf(v, f.y, acc[2 * k + 1]);
                }

                int flush = (j == CHUNK - 1) || (r_next != r_cur) || (idx >= last);
                if (__ballot_sync(0xffffffffu, flush)) {
                    float* dst = out + (size_t)r_cur * D_FEAT + fl * 8;
                    red_add_v4(dst,     acc[0], acc[1], acc[2], acc[3], flush);
                    red_add_v4(dst + 4, acc[4], acc[5], acc[6], acc[7], flush);
                    #pragma unroll
                    for (int k = 0; k < 8; ++k) acc[k] = flush ? 0.f : acc[k];
                }
                r_cur = r_next;
            }
        }
    }
}

extern "C" void kernel_launch(void* const* d_in, const int* in_sizes, int n_in,
                              void* d_out, int out_size) {
    const int*   row = (const int*)d_in[0];
    const int*   col = (const int*)d_in[1];
    const float* val = (const float*)d_in[2];
    const float* x   = (const float*)d_in[3];
    float*       out = (float*)d_out;

    int n_edges = in_sizes[0];
    int n_x     = in_sizes[3];

    {
        int threads = 256;
        int n4 = n_x / 4;
        int n_out4 = out_size / 4;
        int conv_blocks = (n4 + threads - 1) / threads;
        int zero_blocks = (n_out4 + threads - 1) / threads;
        fused_prep_kernel<<<conv_blocks + zero_blocks, threads>>>(
            x, n4, out, n_out4, conv_blocks);
    }
    {
        int threads = 256;  // 8 warps/block; warp-task covers 4*CHUNK = 64 edges
        int n_tasks = (n_edges + 4 * CHUNK - 1) / (4 * CHUNK);
        int blocks = 1216;  // ~152 SMs x 8 resident blocks: persistent, no tail wave
        spmm_edge_chunk_kernel<<<blocks, threads>>>(row, col, val, out,
                                                    n_edges, n_tasks);
    }
}